// round 1
// baseline (speedup 1.0000x reference)
#include <cuda_runtime.h>
#include <cuda_bf16.h>

// Problem constants
#define B_    16
#define CIN_  512
#define COUT_ 3
#define WDIM_ 512
#define HW_   16384   // 128*128
#define HW4_  4096    // HW/4

// 1/sqrt(512)
#define FC_GAIN_     0.044194173824159216f
#define WEIGHT_GAIN_ 0.044194173824159216f
#define CLAMP_       256.0f

// Per-sample modulated 1x1 conv weights: [B][CIN] x float4 (w_o0, w_o1, w_o2, pad)
__device__ float4 g_wmod[B_ * CIN_];

// ---------------------------------------------------------------------------
// Kernel 1: styles + weight modulation.
// grid = (B, 4), block = 128 threads; each thread handles one channel c.
// ---------------------------------------------------------------------------
__global__ void styles_kernel(const float* __restrict__ w,
                              const float* __restrict__ aW,
                              const float* __restrict__ ab,
                              const float* __restrict__ cw) {
    const int b = blockIdx.x;
    const int c = blockIdx.y * blockDim.x + threadIdx.x;   // 0..511

    __shared__ float ws[WDIM_];
    for (int j = threadIdx.x; j < WDIM_; j += blockDim.x)
        ws[j] = w[b * WDIM_ + j];
    __syncthreads();

    const float4* __restrict__ w4 = reinterpret_cast<const float4*>(ws);
    const float4* __restrict__ r0 =
        reinterpret_cast<const float4*>(aW + (size_t)(0 * CIN_ + c) * WDIM_);
    const float4* __restrict__ r1 =
        reinterpret_cast<const float4*>(aW + (size_t)(1 * CIN_ + c) * WDIM_);
    const float4* __restrict__ r2 =
        reinterpret_cast<const float4*>(aW + (size_t)(2 * CIN_ + c) * WDIM_);

    float s0 = 0.f, s1 = 0.f, s2 = 0.f;
#pragma unroll 8
    for (int j = 0; j < WDIM_ / 4; j++) {
        float4 wv = w4[j];
        float4 a0 = r0[j];
        float4 a1 = r1[j];
        float4 a2 = r2[j];
        s0 += wv.x * a0.x + wv.y * a0.y + wv.z * a0.z + wv.w * a0.w;
        s1 += wv.x * a1.x + wv.y * a1.y + wv.z * a1.z + wv.w * a1.w;
        s2 += wv.x * a2.x + wv.y * a2.y + wv.z * a2.z + wv.w * a2.w;
    }

    float m1 = s0 * FC_GAIN_ + ab[0 * CIN_ + c];
    float m2 = s1 * FC_GAIN_ + ab[1 * CIN_ + c];
    float m3 = s2 * FC_GAIN_ + ab[2 * CIN_ + c];
    float st = (m1 * m2 + m3) * WEIGHT_GAIN_;

    g_wmod[b * CIN_ + c] = make_float4(cw[0 * CIN_ + c] * st,
                                       cw[1 * CIN_ + c] * st,
                                       cw[2 * CIN_ + c] * st,
                                       0.f);
}

// ---------------------------------------------------------------------------
// Kernel 2: streaming modulated 1x1 conv (HBM-bound).
// grid = (32, B), block = 128. Each thread owns one float4 pixel group and
// reduces over all 512 input channels.
// ---------------------------------------------------------------------------
__global__ __launch_bounds__(128)
void conv_kernel(const float* __restrict__ x,
                 const float* __restrict__ cb,
                 float* __restrict__ out) {
    const int b = blockIdx.y;
    const int p = blockIdx.x * blockDim.x + threadIdx.x;   // 0..4095 (float4 idx)

    __shared__ float4 swm[CIN_];
    {
        const float4* gw = g_wmod + b * CIN_;
        for (int i = threadIdx.x; i < CIN_; i += blockDim.x)
            swm[i] = gw[i];
    }
    __syncthreads();

    const float4* __restrict__ xb =
        reinterpret_cast<const float4*>(x) + (size_t)b * CIN_ * HW4_ + p;

    float4 a0 = make_float4(0.f, 0.f, 0.f, 0.f);
    float4 a1 = a0;
    float4 a2 = a0;

#pragma unroll 4
    for (int c = 0; c < CIN_; c++) {
        float4 xv = xb[(size_t)c * HW4_];
        float4 wm = swm[c];
        a0.x += xv.x * wm.x; a0.y += xv.y * wm.x; a0.z += xv.z * wm.x; a0.w += xv.w * wm.x;
        a1.x += xv.x * wm.y; a1.y += xv.y * wm.y; a1.z += xv.z * wm.y; a1.w += xv.w * wm.y;
        a2.x += xv.x * wm.z; a2.y += xv.y * wm.z; a2.z += xv.z * wm.z; a2.w += xv.w * wm.z;
    }

    const float b0 = cb[0], b1 = cb[1], b2 = cb[2];

    a0.x = fminf(fmaxf(a0.x + b0, -CLAMP_), CLAMP_);
    a0.y = fminf(fmaxf(a0.y + b0, -CLAMP_), CLAMP_);
    a0.z = fminf(fmaxf(a0.z + b0, -CLAMP_), CLAMP_);
    a0.w = fminf(fmaxf(a0.w + b0, -CLAMP_), CLAMP_);

    a1.x = fminf(fmaxf(a1.x + b1, -CLAMP_), CLAMP_);
    a1.y = fminf(fmaxf(a1.y + b1, -CLAMP_), CLAMP_);
    a1.z = fminf(fmaxf(a1.z + b1, -CLAMP_), CLAMP_);
    a1.w = fminf(fmaxf(a1.w + b1, -CLAMP_), CLAMP_);

    a2.x = fminf(fmaxf(a2.x + b2, -CLAMP_), CLAMP_);
    a2.y = fminf(fmaxf(a2.y + b2, -CLAMP_), CLAMP_);
    a2.z = fminf(fmaxf(a2.z + b2, -CLAMP_), CLAMP_);
    a2.w = fminf(fmaxf(a2.w + b2, -CLAMP_), CLAMP_);

    float4* __restrict__ o =
        reinterpret_cast<float4*>(out) + (size_t)b * COUT_ * HW4_ + p;
    o[0 * HW4_] = a0;
    o[1 * HW4_] = a1;
    o[2 * HW4_] = a2;
}

// ---------------------------------------------------------------------------
// Launch
// inputs (metadata order): x, w, affine_W, affine_b, conv_w, conv_b
// ---------------------------------------------------------------------------
extern "C" void kernel_launch(void* const* d_in, const int* in_sizes, int n_in,
                              void* d_out, int out_size) {
    const float* x  = (const float*)d_in[0];
    const float* w  = (const float*)d_in[1];
    const float* aW = (const float*)d_in[2];
    const float* ab = (const float*)d_in[3];
    const float* cw = (const float*)d_in[4];
    const float* cb = (const float*)d_in[5];
    float* out = (float*)d_out;

    {
        dim3 grid(B_, CIN_ / 128);
        styles_kernel<<<grid, 128>>>(w, aW, ab, cw);
    }
    {
        dim3 grid(HW4_ / 128, B_);
        conv_kernel<<<grid, 128>>>(x, cb, out);
    }
}

// round 2
// speedup vs baseline: 1.2151x; 1.2151x over previous
#include <cuda_runtime.h>
#include <cuda_bf16.h>

#define B_    16
#define CIN_  512
#define COUT_ 3
#define WDIM_ 512
#define HW_   16384
#define HW4_  4096

#define FC_GAIN_     0.044194173824159216f
#define WEIGHT_GAIN_ 0.044194173824159216f
#define CLAMP_       256.0f

// Per-sample modulated 1x1 conv weights: [B][CIN] x float4 (w_o0, w_o1, w_o2, pad)
__device__ float4 g_wmod[B_ * CIN_];

// ---------------------------------------------------------------------------
// Kernel 1: styles + weight modulation. One warp per (b, c).
// grid = (CIN/8, B), block = 256 (8 warps). Lanes stride within the row
// (coalesced float4 loads), warp shfl reduction.
// ---------------------------------------------------------------------------
__global__ __launch_bounds__(256)
void styles_kernel(const float* __restrict__ w,
                   const float* __restrict__ aW,
                   const float* __restrict__ ab,
                   const float* __restrict__ cw) {
    const int warp = threadIdx.x >> 5;
    const int lane = threadIdx.x & 31;
    const int c = blockIdx.x * 8 + warp;      // 0..511
    const int b = blockIdx.y;

    const float4* __restrict__ w4 = reinterpret_cast<const float4*>(w + (size_t)b * WDIM_);
    const float4* __restrict__ r0 = reinterpret_cast<const float4*>(aW + (size_t)(0 * CIN_ + c) * WDIM_);
    const float4* __restrict__ r1 = reinterpret_cast<const float4*>(aW + (size_t)(1 * CIN_ + c) * WDIM_);
    const float4* __restrict__ r2 = reinterpret_cast<const float4*>(aW + (size_t)(2 * CIN_ + c) * WDIM_);

    float s0 = 0.f, s1 = 0.f, s2 = 0.f;
#pragma unroll
    for (int jj = 0; jj < WDIM_ / 4 / 32; jj++) {     // 4 iterations
        const int j = jj * 32 + lane;
        float4 wv = w4[j];
        float4 a0 = r0[j];
        float4 a1 = r1[j];
        float4 a2 = r2[j];
        s0 += wv.x * a0.x + wv.y * a0.y + wv.z * a0.z + wv.w * a0.w;
        s1 += wv.x * a1.x + wv.y * a1.y + wv.z * a1.z + wv.w * a1.w;
        s2 += wv.x * a2.x + wv.y * a2.y + wv.z * a2.z + wv.w * a2.w;
    }

#pragma unroll
    for (int off = 16; off > 0; off >>= 1) {
        s0 += __shfl_xor_sync(0xFFFFFFFF, s0, off);
        s1 += __shfl_xor_sync(0xFFFFFFFF, s1, off);
        s2 += __shfl_xor_sync(0xFFFFFFFF, s2, off);
    }

    if (lane == 0) {
        float m1 = s0 * FC_GAIN_ + ab[0 * CIN_ + c];
        float m2 = s1 * FC_GAIN_ + ab[1 * CIN_ + c];
        float m3 = s2 * FC_GAIN_ + ab[2 * CIN_ + c];
        float st = (m1 * m2 + m3) * WEIGHT_GAIN_;
        g_wmod[b * CIN_ + c] = make_float4(cw[0 * CIN_ + c] * st,
                                           cw[1 * CIN_ + c] * st,
                                           cw[2 * CIN_ + c] * st,
                                           0.f);
    }
}

// ---------------------------------------------------------------------------
// Kernel 2: streaming modulated 1x1 conv.
// grid = (64, B), block = 64. Explicitly batched loads (8 LDG.128 in flight
// per thread) to cover DRAM latency; 1024 blocks for wave balance.
// ---------------------------------------------------------------------------
#define UNR_ 8

__global__ __launch_bounds__(64)
void conv_kernel(const float* __restrict__ x,
                 const float* __restrict__ cb,
                 float* __restrict__ out) {
    const int b = blockIdx.y;
    const int p = blockIdx.x * 64 + threadIdx.x;   // float4 pixel index

    __shared__ float4 swm[CIN_];
    {
        const float4* gw = g_wmod + b * CIN_;
#pragma unroll
        for (int i = 0; i < CIN_ / 64; i++)
            swm[i * 64 + threadIdx.x] = gw[i * 64 + threadIdx.x];
    }
    __syncthreads();

    const float4* __restrict__ xb =
        reinterpret_cast<const float4*>(x) + (size_t)b * CIN_ * HW4_ + p;

    float4 a0 = make_float4(0.f, 0.f, 0.f, 0.f);
    float4 a1 = a0;
    float4 a2 = a0;

    for (int c0 = 0; c0 < CIN_; c0 += UNR_) {
        float4 xv[UNR_];
#pragma unroll
        for (int i = 0; i < UNR_; i++)
            xv[i] = xb[(size_t)(c0 + i) * HW4_];
#pragma unroll
        for (int i = 0; i < UNR_; i++) {
            float4 wm = swm[c0 + i];
            a0.x = fmaf(xv[i].x, wm.x, a0.x);
            a0.y = fmaf(xv[i].y, wm.x, a0.y);
            a0.z = fmaf(xv[i].z, wm.x, a0.z);
            a0.w = fmaf(xv[i].w, wm.x, a0.w);
            a1.x = fmaf(xv[i].x, wm.y, a1.x);
            a1.y = fmaf(xv[i].y, wm.y, a1.y);
            a1.z = fmaf(xv[i].z, wm.y, a1.z);
            a1.w = fmaf(xv[i].w, wm.y, a1.w);
            a2.x = fmaf(xv[i].x, wm.z, a2.x);
            a2.y = fmaf(xv[i].y, wm.z, a2.y);
            a2.z = fmaf(xv[i].z, wm.z, a2.z);
            a2.w = fmaf(xv[i].w, wm.z, a2.w);
        }
    }

    const float b0 = cb[0], b1 = cb[1], b2 = cb[2];

    a0.x = fminf(fmaxf(a0.x + b0, -CLAMP_), CLAMP_);
    a0.y = fminf(fmaxf(a0.y + b0, -CLAMP_), CLAMP_);
    a0.z = fminf(fmaxf(a0.z + b0, -CLAMP_), CLAMP_);
    a0.w = fminf(fmaxf(a0.w + b0, -CLAMP_), CLAMP_);

    a1.x = fminf(fmaxf(a1.x + b1, -CLAMP_), CLAMP_);
    a1.y = fminf(fmaxf(a1.y + b1, -CLAMP_), CLAMP_);
    a1.z = fminf(fmaxf(a1.z + b1, -CLAMP_), CLAMP_);
    a1.w = fminf(fmaxf(a1.w + b1, -CLAMP_), CLAMP_);

    a2.x = fminf(fmaxf(a2.x + b2, -CLAMP_), CLAMP_);
    a2.y = fminf(fmaxf(a2.y + b2, -CLAMP_), CLAMP_);
    a2.z = fminf(fmaxf(a2.z + b2, -CLAMP_), CLAMP_);
    a2.w = fminf(fmaxf(a2.w + b2, -CLAMP_), CLAMP_);

    float4* __restrict__ o =
        reinterpret_cast<float4*>(out) + (size_t)b * COUT_ * HW4_ + p;
    o[0 * HW4_] = a0;
    o[1 * HW4_] = a1;
    o[2 * HW4_] = a2;
}

// ---------------------------------------------------------------------------
// inputs (metadata order): x, w, affine_W, affine_b, conv_w, conv_b
// ---------------------------------------------------------------------------
extern "C" void kernel_launch(void* const* d_in, const int* in_sizes, int n_in,
                              void* d_out, int out_size) {
    const float* x  = (const float*)d_in[0];
    const float* w  = (const float*)d_in[1];
    const float* aW = (const float*)d_in[2];
    const float* ab = (const float*)d_in[3];
    const float* cw = (const float*)d_in[4];
    const float* cb = (const float*)d_in[5];
    float* out = (float*)d_out;

    {
        dim3 grid(CIN_ / 8, B_);
        styles_kernel<<<grid, 256>>>(w, aW, ab, cw);
    }
    {
        dim3 grid(HW4_ / 64, B_);
        conv_kernel<<<grid, 64>>>(x, cb, out);
    }
}

// round 3
// speedup vs baseline: 2.0144x; 1.6578x over previous
#include <cuda_runtime.h>
#include <cuda_bf16.h>
#include <cstdint>

#define B_    16
#define CIN_  512
#define COUT_ 3
#define WDIM_ 512
#define HW_   16384
#define HW4_  4096

#define FC_GAIN_     0.044194173824159216f
#define WEIGHT_GAIN_ 0.044194173824159216f
#define CLAMP_       256.0f

#define CHUNK_ 8
#define NCHUNK_ (CIN_ / CHUNK_)

// Per-sample modulated 1x1 conv weights: [B][CIN] x float4 (w_o0, w_o1, w_o2, pad)
__device__ float4 g_wmod[B_ * CIN_];

__device__ __forceinline__ void cp_async16(uint32_t smem_addr, const void* gptr) {
    asm volatile("cp.async.cg.shared.global [%0], [%1], 16;"
                 :: "r"(smem_addr), "l"(gptr) : "memory");
}

// ---------------------------------------------------------------------------
// Kernel 1: styles + weight modulation. One warp per (b, c).
// ---------------------------------------------------------------------------
__global__ __launch_bounds__(256)
void styles_kernel(const float* __restrict__ w,
                   const float* __restrict__ aW,
                   const float* __restrict__ ab,
                   const float* __restrict__ cw) {
    const int warp = threadIdx.x >> 5;
    const int lane = threadIdx.x & 31;
    const int c = blockIdx.x * 8 + warp;      // 0..511
    const int b = blockIdx.y;

    const float4* __restrict__ w4 = reinterpret_cast<const float4*>(w + (size_t)b * WDIM_);
    const float4* __restrict__ r0 = reinterpret_cast<const float4*>(aW + (size_t)(0 * CIN_ + c) * WDIM_);
    const float4* __restrict__ r1 = reinterpret_cast<const float4*>(aW + (size_t)(1 * CIN_ + c) * WDIM_);
    const float4* __restrict__ r2 = reinterpret_cast<const float4*>(aW + (size_t)(2 * CIN_ + c) * WDIM_);

    float s0 = 0.f, s1 = 0.f, s2 = 0.f;
#pragma unroll
    for (int jj = 0; jj < WDIM_ / 4 / 32; jj++) {     // 4 iterations
        const int j = jj * 32 + lane;
        float4 wv = w4[j];
        float4 a0 = r0[j];
        float4 a1 = r1[j];
        float4 a2 = r2[j];
        s0 += wv.x * a0.x + wv.y * a0.y + wv.z * a0.z + wv.w * a0.w;
        s1 += wv.x * a1.x + wv.y * a1.y + wv.z * a1.z + wv.w * a1.w;
        s2 += wv.x * a2.x + wv.y * a2.y + wv.z * a2.z + wv.w * a2.w;
    }

#pragma unroll
    for (int off = 16; off > 0; off >>= 1) {
        s0 += __shfl_xor_sync(0xFFFFFFFF, s0, off);
        s1 += __shfl_xor_sync(0xFFFFFFFF, s1, off);
        s2 += __shfl_xor_sync(0xFFFFFFFF, s2, off);
    }

    if (lane == 0) {
        float m1 = s0 * FC_GAIN_ + ab[0 * CIN_ + c];
        float m2 = s1 * FC_GAIN_ + ab[1 * CIN_ + c];
        float m3 = s2 * FC_GAIN_ + ab[2 * CIN_ + c];
        float st = (m1 * m2 + m3) * WEIGHT_GAIN_;
        g_wmod[b * CIN_ + c] = make_float4(cw[0 * CIN_ + c] * st,
                                           cw[1 * CIN_ + c] * st,
                                           cw[2 * CIN_ + c] * st,
                                           0.f);
    }
}

// ---------------------------------------------------------------------------
// Kernel 2: streaming modulated 1x1 conv, cp.async double-buffered.
// grid = (64, B), block = 64. Each thread owns one float4 pixel group;
// channel chunks of 8 are staged through smem by cp.async. Each thread
// reads back only its own slots -> no barriers in the main loop; the
// prefetch depth (8 KB/block outstanding) lives in the LSU, not registers.
// ---------------------------------------------------------------------------
__global__ __launch_bounds__(64)
void conv_kernel(const float* __restrict__ x,
                 const float* __restrict__ cb,
                 float* __restrict__ out) {
    const int b = blockIdx.y;
    const int t = threadIdx.x;
    const int p = blockIdx.x * 64 + t;            // float4 pixel index

    __shared__ float4 swm[CIN_];
    __shared__ float4 stage[2][CHUNK_][64];

    {
        const float4* gw = g_wmod + b * CIN_;
#pragma unroll
        for (int i = 0; i < CIN_ / 64; i++)
            swm[i * 64 + t] = gw[i * 64 + t];
    }
    __syncthreads();

    const float4* __restrict__ xb =
        reinterpret_cast<const float4*>(x) + (size_t)b * CIN_ * HW4_ + p;

    const uint32_t stbase = (uint32_t)__cvta_generic_to_shared(&stage[0][0][t]);
    // stage[s][i][t]: +s*CHUNK_*1024 + i*1024 bytes from stbase

    // Prologue: prefetch chunk 0 into buffer 0
#pragma unroll
    for (int i = 0; i < CHUNK_; i++)
        cp_async16(stbase + i * 1024, xb + (size_t)i * HW4_);
    asm volatile("cp.async.commit_group;" ::: "memory");

    float4 a0 = make_float4(0.f, 0.f, 0.f, 0.f);
    float4 a1 = a0;
    float4 a2 = a0;

    for (int k = 0; k < NCHUNK_; k++) {
        const int cur = k & 1;
        if (k + 1 < NCHUNK_) {
            const int c1 = (k + 1) * CHUNK_;
            const uint32_t sb = stbase + (cur ^ 1) * (CHUNK_ * 1024);
#pragma unroll
            for (int i = 0; i < CHUNK_; i++)
                cp_async16(sb + i * 1024, xb + (size_t)(c1 + i) * HW4_);
            asm volatile("cp.async.commit_group;" ::: "memory");
            asm volatile("cp.async.wait_group 1;" ::: "memory");
        } else {
            asm volatile("cp.async.wait_group 0;" ::: "memory");
        }

#pragma unroll
        for (int i = 0; i < CHUNK_; i++) {
            float4 xv = stage[cur][i][t];
            float4 wm = swm[k * CHUNK_ + i];
            a0.x = fmaf(xv.x, wm.x, a0.x);
            a0.y = fmaf(xv.y, wm.x, a0.y);
            a0.z = fmaf(xv.z, wm.x, a0.z);
            a0.w = fmaf(xv.w, wm.x, a0.w);
            a1.x = fmaf(xv.x, wm.y, a1.x);
            a1.y = fmaf(xv.y, wm.y, a1.y);
            a1.z = fmaf(xv.z, wm.y, a1.z);
            a1.w = fmaf(xv.w, wm.y, a1.w);
            a2.x = fmaf(xv.x, wm.z, a2.x);
            a2.y = fmaf(xv.y, wm.z, a2.y);
            a2.z = fmaf(xv.z, wm.z, a2.z);
            a2.w = fmaf(xv.w, wm.z, a2.w);
        }
    }

    const float b0 = cb[0], b1 = cb[1], b2 = cb[2];

    a0.x = fminf(fmaxf(a0.x + b0, -CLAMP_), CLAMP_);
    a0.y = fminf(fmaxf(a0.y + b0, -CLAMP_), CLAMP_);
    a0.z = fminf(fmaxf(a0.z + b0, -CLAMP_), CLAMP_);
    a0.w = fminf(fmaxf(a0.w + b0, -CLAMP_), CLAMP_);

    a1.x = fminf(fmaxf(a1.x + b1, -CLAMP_), CLAMP_);
    a1.y = fminf(fmaxf(a1.y + b1, -CLAMP_), CLAMP_);
    a1.z = fminf(fmaxf(a1.z + b1, -CLAMP_), CLAMP_);
    a1.w = fminf(fmaxf(a1.w + b1, -CLAMP_), CLAMP_);

    a2.x = fminf(fmaxf(a2.x + b2, -CLAMP_), CLAMP_);
    a2.y = fminf(fmaxf(a2.y + b2, -CLAMP_), CLAMP_);
    a2.z = fminf(fmaxf(a2.z + b2, -CLAMP_), CLAMP_);
    a2.w = fminf(fmaxf(a2.w + b2, -CLAMP_), CLAMP_);

    float4* __restrict__ o =
        reinterpret_cast<float4*>(out) + (size_t)b * COUT_ * HW4_ + p;
    o[0 * HW4_] = a0;
    o[1 * HW4_] = a1;
    o[2 * HW4_] = a2;
}

// ---------------------------------------------------------------------------
// inputs (metadata order): x, w, affine_W, affine_b, conv_w, conv_b
// ---------------------------------------------------------------------------
extern "C" void kernel_launch(void* const* d_in, const int* in_sizes, int n_in,
                              void* d_out, int out_size) {
    const float* x  = (const float*)d_in[0];
    const float* w  = (const float*)d_in[1];
    const float* aW = (const float*)d_in[2];
    const float* ab = (const float*)d_in[3];
    const float* cw = (const float*)d_in[4];
    const float* cb = (const float*)d_in[5];
    float* out = (float*)d_out;

    {
        dim3 grid(CIN_ / 8, B_);
        styles_kernel<<<grid, 256>>>(w, aW, ab, cw);
    }
    {
        dim3 grid(HW4_ / 64, B_);
        conv_kernel<<<grid, 64>>>(x, cb, out);
    }
}